// round 10
// baseline (speedup 1.0000x reference)
#include <cuda_runtime.h>
#include <cuda_bf16.h>
#include <math.h>
#include <stdint.h>

// Problem constants
#define Bn    8
#define Tn    2048
#define Dn    1024
#define DSn   256
#define KLn   32
#define WINn  3
#define Mtot  (Bn * Tn)      // 16384
// SCALE = sqrt(DS) = 16

// Scratch
__device__ float g_Q[Mtot * DSn];                    // 16 MB
__device__ float g_K[Mtot * DSn];                    // 16 MB
__device__ __nv_bfloat16 g_Xhi[Mtot * Dn];           // 32 MB
__device__ __nv_bfloat16 g_Xlo[Mtot * Dn];           // 32 MB
#define KTOT 3072
__device__ __nv_bfloat16 g_Wsp[512 * KTOT];          // 3 MB: [n][k''], k''=[hi|lo|hi]

__device__ __forceinline__ uint32_t smem_u32(const void* p) {
    uint32_t a;
    asm("{ .reg .u64 t; cvta.to.shared.u64 t, %1; cvt.u32.u64 %0, t; }" : "=r"(a) : "l"(p));
    return a;
}
__device__ __forceinline__ void cp16(uint32_t dst, const void* src) {
    asm volatile("cp.async.cg.shared.global [%0], [%1], 16;" :: "r"(dst), "l"(src));
}
#define CP_COMMIT() asm volatile("cp.async.commit_group;" ::: "memory")
#define CP_WAIT(n)  asm volatile("cp.async.wait_group %0;" :: "n"(n) : "memory")

// ---------------------------------------------------------------------------
// Convert X (fp32) -> bf16 hi/lo
// ---------------------------------------------------------------------------
__global__ void convert_x_kernel(const float* __restrict__ X) {
    int idx = blockIdx.x * blockDim.x + threadIdx.x;     // float4 index
    float4 v = *(const float4*)(X + (size_t)idx * 4);
    __nv_bfloat16 hx = __float2bfloat16(v.x);
    __nv_bfloat16 hy = __float2bfloat16(v.y);
    __nv_bfloat16 hz = __float2bfloat16(v.z);
    __nv_bfloat16 hw = __float2bfloat16(v.w);
    __nv_bfloat162 hp0(hx, hy), hp1(hz, hw);
    __nv_bfloat162 lp0(__float2bfloat16(v.x - __bfloat162float(hx)),
                       __float2bfloat16(v.y - __bfloat162float(hy)));
    __nv_bfloat162 lp1(__float2bfloat16(v.z - __bfloat162float(hz)),
                       __float2bfloat16(v.w - __bfloat162float(hw)));
    *(uint2*)(g_Xhi + (size_t)idx * 4) = make_uint2(*(uint32_t*)&hp0, *(uint32_t*)&hp1);
    *(uint2*)(g_Xlo + (size_t)idx * 4) = make_uint2(*(uint32_t*)&lp0, *(uint32_t*)&lp1);
}

// ---------------------------------------------------------------------------
// Build B'' = [Whi | Wlo | Whi] transposed to [n][k''] (n<256: WQ, else WK)
// ---------------------------------------------------------------------------
__global__ void convert_w_kernel(const float* __restrict__ WQ, const float* __restrict__ WK) {
    int idx = blockIdx.x * blockDim.x + threadIdx.x;     // 0 .. 512*3072-1
    int n  = idx / KTOT;
    int kk = idx - n * KTOT;
    int reg = kk >> 10;            // 0:hi 1:lo 2:hi
    int k   = kk & 1023;
    float x = (n < 256) ? WQ[k * 256 + n] : WK[k * 256 + (n - 256)];
    __nv_bfloat16 hi = __float2bfloat16(x);
    __nv_bfloat16 outv = (reg == 1) ? __float2bfloat16(x - __bfloat162float(hi)) : hi;
    g_Wsp[idx] = outv;
}

// ---------------------------------------------------------------------------
// bf16 mma.sync GEMM with 3-stage cp.async pipeline (prefetch hoisted).
// [Q|K](16384 x 512) over K''=3072. CTA tile 128x128, BK=64, 8 warps (2x4).
// ---------------------------------------------------------------------------
#define BM 128
#define BN 128
#define BK 64
#define PAD 8
#define LDS_A (BK + PAD)          // 72 bf16 = 144 B row stride
#define TILE_E (BM * LDS_A)       // bf16 elems per A/B stage (9216)
#define STG_B  (TILE_E * 2)       // bytes per stage
#define NIT    (KTOT / BK)        // 48
#define NSTG   3
#define SMEM_GEMM (NSTG * 2 * TILE_E * 2)  // 110592 B

__global__ __launch_bounds__(256, 2)
void qk_mma_kernel() {
    extern __shared__ __nv_bfloat16 smg[];
    __nv_bfloat16* As = smg;                      // [NSTG][TILE_E]
    __nv_bfloat16* Bs = smg + NSTG * TILE_E;      // [NSTG][TILE_E]

    const int tid  = threadIdx.x;
    const int wid  = tid >> 5;
    const int lane = tid & 31;
    const int wm = wid & 1;
    const int wn = wid >> 1;
    const int mbase = wm * 64;
    const int nbase = wn * 32;
    const int mtile = blockIdx.y * BM;
    const int ntile = blockIdx.x * BN;

    const int g = lane >> 3;
    const int r = lane & 7;

    float d[4][4][4];
#pragma unroll
    for (int i = 0; i < 4; i++)
#pragma unroll
        for (int j = 0; j < 4; j++)
#pragma unroll
            for (int q = 0; q < 4; q++) d[i][j][q] = 0.f;

    const uint32_t as_base = smem_u32(As);
    const uint32_t bs_base = smem_u32(Bs);

    const int lrow[4] = { (0 * 256 + tid) >> 3, (1 * 256 + tid) >> 3,
                          (2 * 256 + tid) >> 3, (3 * 256 + tid) >> 3 };
    const int lc8 = (tid & 7) * 8;

    auto issue_loads = [&](int it, int s) {
        const int kb = it * BK;
        const __nv_bfloat16* Asrc = (kb < 2048) ? g_Xhi : g_Xlo;
        const int ksrc = kb & 1023;
#pragma unroll
        for (int i = 0; i < 4; i++) {
            int row = lrow[i];
            cp16(as_base + (uint32_t)(s * TILE_E + row * LDS_A + lc8) * 2u,
                 Asrc + (size_t)(mtile + row) * Dn + ksrc + lc8);
        }
#pragma unroll
        for (int i = 0; i < 4; i++) {
            int row = lrow[i];
            cp16(bs_base + (uint32_t)(s * TILE_E + row * LDS_A + lc8) * 2u,
                 g_Wsp + (size_t)(ntile + row) * KTOT + kb + lc8);
        }
        CP_COMMIT();
    };

    issue_loads(0, 0);
    issue_loads(1, 1);

    for (int it = 0; it < NIT; it++) {
        if (it < NIT - 1) { CP_WAIT(1); } else { CP_WAIT(0); }
        __syncthreads();
        // Prefetch it+2 now: barrier above guarantees stage (it+2)%3's last
        // consumer (iteration it-1) has completed in every warp.
        if (it + 2 < NIT) issue_loads(it + 2, (it + 2) % NSTG);

        const int cur = it % NSTG;
        const uint32_t as_s = as_base + (uint32_t)cur * STG_B;
        const uint32_t bs_s = bs_base + (uint32_t)cur * STG_B;

#pragma unroll
        for (int ks = 0; ks < BK / 16; ks++) {
            const int k0 = ks * 16;
            uint32_t a[4][4];
#pragma unroll
            for (int mf = 0; mf < 4; mf++) {
                int row = mbase + mf * 16 + (g & 1) * 8 + r;
                int col = k0 + (g >> 1) * 8;
                uint32_t addr = as_s + (uint32_t)(row * LDS_A + col) * 2u;
                asm volatile("ldmatrix.sync.aligned.m8n8.x4.shared.b16 {%0,%1,%2,%3}, [%4];"
                             : "=r"(a[mf][0]), "=r"(a[mf][1]), "=r"(a[mf][2]), "=r"(a[mf][3])
                             : "r"(addr));
            }
            uint32_t b[4][2];
#pragma unroll
            for (int nh = 0; nh < 2; nh++) {
                int row = nbase + nh * 16 + (g >> 1) * 8 + r;
                int col = k0 + (g & 1) * 8;
                uint32_t addr = bs_s + (uint32_t)(row * LDS_A + col) * 2u;
                uint32_t t0, t1, t2, t3;
                asm volatile("ldmatrix.sync.aligned.m8n8.x4.shared.b16 {%0,%1,%2,%3}, [%4];"
                             : "=r"(t0), "=r"(t1), "=r"(t2), "=r"(t3) : "r"(addr));
                b[nh * 2 + 0][0] = t0; b[nh * 2 + 0][1] = t1;
                b[nh * 2 + 1][0] = t2; b[nh * 2 + 1][1] = t3;
            }
#pragma unroll
            for (int mf = 0; mf < 4; mf++)
#pragma unroll
                for (int nf = 0; nf < 4; nf++) {
                    asm volatile(
                        "mma.sync.aligned.m16n8k16.row.col.f32.bf16.bf16.f32 "
                        "{%0,%1,%2,%3}, {%4,%5,%6,%7}, {%8,%9}, {%0,%1,%2,%3};"
                        : "+f"(d[mf][nf][0]), "+f"(d[mf][nf][1]),
                          "+f"(d[mf][nf][2]), "+f"(d[mf][nf][3])
                        : "r"(a[mf][0]), "r"(a[mf][1]), "r"(a[mf][2]), "r"(a[mf][3]),
                          "r"(b[nf][0]), "r"(b[nf][1]));
                }
        }
    }

    float* dst = (ntile < 256) ? g_Q : g_K;
    const int ncol0 = (ntile & 255) + nbase;
#pragma unroll
    for (int mf = 0; mf < 4; mf++) {
#pragma unroll
        for (int nf = 0; nf < 4; nf++) {
            int row = mtile + mbase + mf * 16 + (lane >> 2);
            int col = ncol0 + nf * 8 + (lane & 3) * 2;
            *(float2*)(dst + (size_t)row * DSn + col) =
                make_float2(d[mf][nf][0], d[mf][nf][1]);
            *(float2*)(dst + (size_t)(row + 8) * DSn + col) =
                make_float2(d[mf][nf][2], d[mf][nf][3]);
        }
    }
}

// ----------------------------------------------------------------------------
// Stage 2 (R7-proven version): 8 t's per block, 256 threads, static smem.
//  Phase 1: warp w -> band softmax weights for t = t0+w -> coef[w][*].
//  Phase 2: warp w owns d-slice [w*128, w*128+128); loads the block's 14
//           unique h rows once, accumulates ctx for all 8 t's in registers.
//  Phase 3: cooperative projection over same d-slice; partials to smem.
//  Phase 4: warp w reduces 8 partials for its t, softmax over k=lane.
// ----------------------------------------------------------------------------
__global__ __launch_bounds__(256)
void ctx_proj_kernel(const float* __restrict__ h,
                     const float* __restrict__ tau,
                     const float* __restrict__ Wp,
                     float* __restrict__ out)
{
    __shared__ float ctx_sh[8 * Dn];        // 32 KB
    __shared__ float part[8][8][KLn];       // 8 KB
    __shared__ float coef[8][8];            // [tt][i] band weights

    const int b    = blockIdx.y;
    const int t0   = blockIdx.x * 8;
    const int w    = threadIdx.x >> 5;
    const int lane = threadIdx.x & 31;
    const int t    = t0 + w;

    const float inv_tau = 1.0f / tau[0];    // hoisted gmem load

    // ---- Phase 1: banded scores + softmax weights for t = t0 + w ----
    {
        const float* Qt = g_Q + ((size_t)(b * Tn + t)) * DSn + lane * 8;
        const float4 q0 = *(const float4*)(Qt);
        const float4 q1 = *(const float4*)(Qt + 4);

        float a[7];
#pragma unroll
        for (int i = 0; i < 7; i++) {
            const int s  = t - WINn + i;
            const int sc = min(max(s, 0), Tn - 1);
            const float* Ks = g_K + ((size_t)(b * Tn + sc)) * DSn + lane * 8;
            const float4 k0 = *(const float4*)(Ks);
            const float4 k1 = *(const float4*)(Ks + 4);
            float p = q0.x*k0.x + q0.y*k0.y + q0.z*k0.z + q0.w*k0.w
                    + q1.x*k1.x + q1.y*k1.y + q1.z*k1.z + q1.w*k1.w;
#pragma unroll
            for (int off = 16; off; off >>= 1)
                p += __shfl_xor_sync(0xffffffffu, p, off);
            a[i] = (s >= 0 && s < Tn) ? p * (1.0f / 16.0f) : -INFINITY;
        }

        float m = a[0];
#pragma unroll
        for (int i = 1; i < 7; i++) m = fmaxf(m, a[i]);
        float sum = 0.f;
#pragma unroll
        for (int i = 0; i < 7; i++) { a[i] = expf(a[i] - m); sum += a[i]; }
        const float inv = 1.0f / sum;
        if (lane < 7) coef[w][lane] = a[lane] * inv;
    }
    __syncthreads();

    // ---- Phase 2: ctx for all 8 t's over d-slice [w*128, w*128+128) ----
    {
        const int d4 = w * 128 + lane * 4;
        const float* hb = h + (size_t)b * Tn * Dn;

        float4 acc[8];
#pragma unroll
        for (int tt = 0; tt < 8; tt++) acc[tt] = make_float4(0.f, 0.f, 0.f, 0.f);

#pragma unroll
        for (int si = 0; si < 14; si++) {
            const int srow = min(max(t0 - WINn + si, 0), Tn - 1);
            const float4 hv = *(const float4*)(hb + (size_t)srow * Dn + d4);
#pragma unroll
            for (int tt = 0; tt < 8; tt++) {
                if (si - tt >= 0 && si - tt <= 6) {          // compile-time pruned
                    const float c = coef[tt][si - tt];       // smem broadcast
                    acc[tt].x = fmaf(c, hv.x, acc[tt].x);
                    acc[tt].y = fmaf(c, hv.y, acc[tt].y);
                    acc[tt].z = fmaf(c, hv.z, acc[tt].z);
                    acc[tt].w = fmaf(c, hv.w, acc[tt].w);
                }
            }
        }
#pragma unroll
        for (int tt = 0; tt < 8; tt++)
            *(float4*)&ctx_sh[tt * Dn + d4] = acc[tt];
    }
    __syncthreads();

    // ---- Phase 3: cooperative projection, warp w covers d in [w*128, +128) ----
    {
        const int d0 = w * 128;
        float acc[8];
#pragma unroll
        for (int tt = 0; tt < 8; tt++) acc[tt] = 0.f;

#pragma unroll 4
        for (int ds = 0; ds < 128; ds += 4) {
            const int dd = d0 + ds;
            const float w0 = Wp[(dd + 0) * KLn + lane];
            const float w1 = Wp[(dd + 1) * KLn + lane];
            const float w2 = Wp[(dd + 2) * KLn + lane];
            const float w3 = Wp[(dd + 3) * KLn + lane];
#pragma unroll
            for (int tt = 0; tt < 8; tt++) {
                const float4 cv = *(const float4*)&ctx_sh[tt * Dn + dd];
                float s0 = fmaf(cv.x, w0, fmaf(cv.y, w1, 0.f));
                float s1 = fmaf(cv.z, w2, fmaf(cv.w, w3, 0.f));
                acc[tt] += s0 + s1;
            }
        }
#pragma unroll
        for (int tt = 0; tt < 8; tt++) part[w][tt][lane] = acc[tt];
    }
    __syncthreads();

    // ---- Phase 4: warp w reduces t = t0 + w, softmax over k = lane ----
    float s = 0.f;
#pragma unroll
    for (int ww = 0; ww < 8; ww++) s += part[ww][w][lane];
    const float logit = s * inv_tau;

    float mm = logit;
#pragma unroll
    for (int off = 16; off; off >>= 1)
        mm = fmaxf(mm, __shfl_xor_sync(0xffffffffu, mm, off));
    const float e = expf(logit - mm);
    float ss = e;
#pragma unroll
    for (int off = 16; off; off >>= 1)
        ss += __shfl_xor_sync(0xffffffffu, ss, off);

    out[((size_t)(b * Tn + t)) * KLn + lane] = e / ss;
}

// ----------------------------------------------------------------------------
// Launch
// ----------------------------------------------------------------------------
extern "C" void kernel_launch(void* const* d_in, const int* in_sizes, int n_in,
                              void* d_out, int out_size)
{
    const float* h   = (const float*)d_in[0];
    const float* tau = (const float*)d_in[1];
    const float* WQ  = (const float*)d_in[2];
    const float* WK  = (const float*)d_in[3];
    const float* Wp  = (const float*)d_in[4];
    float* out = (float*)d_out;

    cudaFuncSetAttribute(qk_mma_kernel,
                         cudaFuncAttributeMaxDynamicSharedMemorySize, SMEM_GEMM);

    convert_x_kernel<<<(Mtot * Dn / 4) / 256, 256>>>(h);
    convert_w_kernel<<<(512 * KTOT) / 256, 256>>>(WQ, WK);

    dim3 g1(512 / BN, Mtot / BM);      // (4, 128)
    qk_mma_kernel<<<g1, 256, SMEM_GEMM>>>();

    dim3 g2(Tn / 8, Bn);
    ctx_proj_kernel<<<g2, 256>>>(h, tau, Wp, out);
}